// round 3
// baseline (speedup 1.0000x reference)
#include <cuda_runtime.h>
#include <math.h>
#include <stdint.h>

// RandomizedOscillatorsNetwork: B=128, T=1024, I=64, H=512
//   u = x @ x2h + bias
//   per step: hz += DT*(tanh(u_t + hy@h2h) - gamma*hy - epsilon*hz); hy += DT*hz
// Decomposition: 16 clusters x 8 CTAs. Cluster owns 8 batch rows; CTA owns 64 H-columns
// with its [576 x 64] weight slice (h2h || x2h) resident in SMEM. Per-step hy exchange
// via L2 (double-buffered __device__ array) + one barrier.cluster.

#define DTc 0.042f
#define Bn 128
#define Tn 1024
#define In 64
#define Hn 512
#define CLUSTER 8
#define HC 64
#define BB 8
#define KTOT 576     // H + I
#define NT 256
#define KC 16        // k-split chunks
#define KS 36        // k per chunk (16*36 = 576)
#define VP 6         // float2 pitch per k-row of the v (hy||x) buffer

#define W_BYTES   (KTOT*HC*4)          // 147456
#define V2_OFF    (W_BYTES)
#define V2_BYTES  (KTOT*VP*8)          // 27648
#define RED_OFF   (V2_OFF + V2_BYTES)  // 175104
#define RED_BYTES (KC*256*8)           // 32768
#define SMEM_BYTES (RED_OFF + RED_BYTES) // 207872

typedef unsigned long long u64;

// double-buffered per-cluster hy exchange: [buf][cluster][h][pair] as float2 {hy[2p], hy[2p+1]}
__device__ float2 g_hy[2][16][Hn][4];

__device__ __forceinline__ u64 pack2(float lo, float hi) {
    u64 r; asm("mov.b64 %0, {%1, %2};" : "=l"(r) : "f"(lo), "f"(hi)); return r;
}
__device__ __forceinline__ void unpack2(u64 v, float& lo, float& hi) {
    asm("mov.b64 {%0, %1}, %2;" : "=f"(lo), "=f"(hi) : "l"(v));
}
__device__ __forceinline__ u64 ffma2(u64 a, u64 b, u64 c) {
    u64 d; asm("fma.rn.f32x2 %0, %1, %2, %3;" : "=l"(d) : "l"(a), "l"(b), "l"(c)); return d;
}

__global__ __launch_bounds__(NT, 1) __cluster_dims__(CLUSTER, 1, 1)
void ron_kernel(const float* __restrict__ x, const float* __restrict__ x2h,
                const float* __restrict__ h2h, const float* __restrict__ bias,
                const float* __restrict__ gam, const float* __restrict__ eps,
                float* __restrict__ out, long long out_elems)
{
    extern __shared__ char smem[];
    float*  W   = (float*)smem;                  // [KTOT][64] k-major, pitch 64 floats
    float2* v2  = (float2*)(smem + V2_OFF);      // [KTOT][VP] pairs of (hy||x), first 4 used
    u64*    red = (u64*)(smem + RED_OFF);        // [KC][256] split-K partials (packed f32x2)

    const int tid  = threadIdx.x;
    const int cl   = blockIdx.x >> 3;   // cluster id 0..15
    const int rank = blockIdx.x & 7;    // CTA rank in cluster
    const int c0   = rank * HC;         // this CTA's H-column base
    const int b0   = cl * BB;           // this cluster's batch base

    // ---- prologue: load resident weight slice W[k][j] = (k<H ? h2h[k][c0+j] : x2h[k-H][c0+j])
    for (int idx = tid; idx < KTOT*HC; idx += NT) {
        int k = idx >> 6, j = idx & 63;
        W[idx] = (k < Hn) ? h2h[(size_t)k*Hn + c0 + j] : x2h[(size_t)(k - Hn)*Hn + c0 + j];
    }
    // zero v buffer (hy part starts at 0; x part overwritten each step)
    for (int idx = tid; idx < KTOT*VP; idx += NT)
        v2[idx] = make_float2(0.f, 0.f);

    // epilogue-thread constants: thread 'tid' owns output pair p=(tid>>6) at column col=(tid&63)
    const int col = tid & 63, p = tid >> 6;
    const int hg  = c0 + col;
    const float bia = bias[hg], ga = gam[hg], ep = eps[hg];
    float hzA = 0.f, hzB = 0.f;

    // GEMM thread mapping: 16 col-groups x 16 k-chunks
    const int cg = tid & 15, kc = tid >> 4;
    const int kb = kc * KS;

    // x prefetch mapping: thread (bx, i2) loads x[b0+bx][t][2*i2 .. 2*i2+1]
    const int bx = tid >> 5, i2 = tid & 31;
    const float* xp = x + ((size_t)(b0 + bx) * Tn) * In + 2*i2;
    float2 xr = *(const float2*)xp;  // t = 0

    const size_t BTH = (size_t)Bn * Tn * Hn;
    const bool writeFinal = (out_elems >= (long long)(BTH + (size_t)Bn * Hn));

    __syncthreads();

    for (int t = 0; t < Tn; t++) {
        // (a) store this step's x rows into v2 (pair-interleaved)
        {
            float* vb = (float*)(v2 + (size_t)(Hn + 2*i2)*VP + (bx >> 1)) + (bx & 1);
            vb[0]      = xr.x;
            vb[2*VP]   = xr.y;   // next k-row = +VP float2 = +2*VP floats
        }
        // (b) pull full cluster hy (written last step) from L2 into v2
        if (t > 0) {
            const float4* src = (const float4*)&g_hy[(t - 1) & 1][cl][0][0]; // 1024 x 16B
            #pragma unroll
            for (int m = 0; m < 4; m++) {
                int c  = tid + NT*m;          // 0..1023
                int kk = c >> 1, pp = (c & 1) << 1;
                float4 vv = src[c];
                *(float4*)(v2 + (size_t)kk*VP + pp) = vv;
            }
        }
        __syncthreads();

        // (c) GEMM: acc[pair][cc] over this thread's 36-k slice, packed f32x2 (2 batch rows/op)
        u64 a00=0ull,a01=0ull,a02=0ull,a03=0ull;
        u64 a10=0ull,a11=0ull,a12=0ull,a13=0ull;
        u64 a20=0ull,a21=0ull,a22=0ull,a23=0ull;
        u64 a30=0ull,a31=0ull,a32=0ull,a33=0ull;
        {
            const float*  Wr = W + kb*HC + cg*4;
            const float2* vr = v2 + (size_t)kb*VP;
            #pragma unroll 4
            for (int kk = 0; kk < KS; kk++) {
                float4 wv = *(const float4*)(Wr + kk*HC);
                const ulonglong2* hv = (const ulonglong2*)(vr + (size_t)kk*VP);
                ulonglong2 hA = hv[0];   // pairs 0,1
                ulonglong2 hB = hv[1];   // pairs 2,3
                u64 w0 = pack2(wv.x, wv.x), w1 = pack2(wv.y, wv.y);
                u64 w2 = pack2(wv.z, wv.z), w3 = pack2(wv.w, wv.w);
                a00 = ffma2(hA.x, w0, a00); a01 = ffma2(hA.x, w1, a01);
                a02 = ffma2(hA.x, w2, a02); a03 = ffma2(hA.x, w3, a03);
                a10 = ffma2(hA.y, w0, a10); a11 = ffma2(hA.y, w1, a11);
                a12 = ffma2(hA.y, w2, a12); a13 = ffma2(hA.y, w3, a13);
                a20 = ffma2(hB.x, w0, a20); a21 = ffma2(hB.x, w1, a21);
                a22 = ffma2(hB.x, w2, a22); a23 = ffma2(hB.x, w3, a23);
                a30 = ffma2(hB.y, w0, a30); a31 = ffma2(hB.y, w1, a31);
                a32 = ffma2(hB.y, w2, a32); a33 = ffma2(hB.y, w3, a33);
            }
        }
        // (d) stage split-K partials
        {
            u64* rb = red + kc*256 + cg*4;
            ulonglong2 t0, t1;
            t0.x=a00; t0.y=a01; t1.x=a02; t1.y=a03;
            *(ulonglong2*)(rb +   0) = t0; *(ulonglong2*)(rb +   0 + 2) = t1;
            t0.x=a10; t0.y=a11; t1.x=a12; t1.y=a13;
            *(ulonglong2*)(rb +  64) = t0; *(ulonglong2*)(rb +  64 + 2) = t1;
            t0.x=a20; t0.y=a21; t1.x=a22; t1.y=a23;
            *(ulonglong2*)(rb + 128) = t0; *(ulonglong2*)(rb + 128 + 2) = t1;
            t0.x=a30; t0.y=a31; t1.x=a32; t1.y=a33;
            *(ulonglong2*)(rb + 192) = t0; *(ulonglong2*)(rb + 192 + 2) = t1;
        }
        __syncthreads();

        // (e) reduce + pointwise oscillator update + outputs
        {
            float sA = 0.f, sB = 0.f;
            #pragma unroll
            for (int q = 0; q < KC; q++) {
                float lo, hi; unpack2(red[q*256 + tid], lo, hi);
                sA += lo; sB += hi;
            }
            float2 hyv = v2[(size_t)hg*VP + p];
            float tA = tanhf(sA + bia);
            float tB = tanhf(sB + bia);
            hzA += DTc * (tA - ga*hyv.x - ep*hzA);
            hzB += DTc * (tB - ga*hyv.y - ep*hzB);
            float hyA = hyv.x + DTc * hzA;
            float hyB = hyv.y + DTc * hzB;
            size_t oA = ((size_t)(b0 + 2*p) * Tn + t) * Hn + hg;
            out[oA]                   = hyA;
            out[oA + (size_t)Tn*Hn]   = hyB;
            g_hy[t & 1][cl][hg][p] = make_float2(hyA, hyB);
            if (t == Tn - 1 && writeFinal) {
                out[BTH + (size_t)(b0 + 2*p)     * Hn + hg] = hyA;
                out[BTH + (size_t)(b0 + 2*p + 1) * Hn + hg] = hyB;
            }
        }
        // prefetch next step's x
        {
            int tn = (t + 1 < Tn) ? (t + 1) : t;
            xr = *(const float2*)(xp + (size_t)tn * In);
        }
        // (f) cluster barrier: release our g_hy STGs, acquire peers'
        asm volatile("barrier.cluster.arrive.aligned;" ::: "memory");
        asm volatile("barrier.cluster.wait.aligned;"   ::: "memory");
    }
}

extern "C" void kernel_launch(void* const* d_in, const int* in_sizes, int n_in,
                              void* d_out, int out_size) {
    const float* x    = (const float*)d_in[0];
    const float* x2h  = (const float*)d_in[1];
    const float* h2h  = (const float*)d_in[2];
    const float* bias = (const float*)d_in[3];
    const float* gam  = (const float*)d_in[4];
    const float* eps  = (const float*)d_in[5];
    float* out = (float*)d_out;
    (void)in_sizes; (void)n_in;

    cudaFuncSetAttribute(ron_kernel, cudaFuncAttributeMaxDynamicSharedMemorySize, SMEM_BYTES);
    ron_kernel<<<128, NT, SMEM_BYTES>>>(x, x2h, h2h, bias, gam, eps, out, (long long)out_size);
}